// round 1
// baseline (speedup 1.0000x reference)
#include <cuda_runtime.h>

#define BB 4
#define SEQ 4096
#define DIM 1024
#define RANK 64
#define NROW (BB * SEQ)   // 16384

// Scratch (allocation-free rule: __device__ globals)
__device__ float g_p[NROW * RANK];   // projected vectors, 4 MB
__device__ float g_sq[NROW];         // row squared norms

// ---- packed f32x2 helpers (sm_103a: 2x fp32 FMA throughput, PTX-only) ----
__device__ __forceinline__ unsigned long long pack2(float x) {
    unsigned long long r;
    asm("mov.b64 %0, {%1, %1};" : "=l"(r) : "f"(x));
    return r;
}
__device__ __forceinline__ void ffma2(unsigned long long& d,
                                      unsigned long long a,
                                      unsigned long long b) {
    asm("fma.rn.f32x2 %0, %1, %2, %0;" : "+l"(d) : "l"(a), "l"(b));
}
__device__ __forceinline__ float2 unpack2(unsigned long long v) {
    float2 f;
    asm("mov.b64 {%0, %1}, %2;" : "=f"(f.x), "=f"(f.y) : "l"(v));
    return f;
}

// ============================================================
// Kernel A: p = x @ proj   [16384,1024] @ [1024,64] -> [16384,64]
// 128 rows x 64 cols per CTA, 256 threads, 8x4 micro-tile.
// ============================================================
__global__ void __launch_bounds__(256) proj_kernel(const float* __restrict__ x,
                                                   const float* __restrict__ proj) {
    __shared__ float xs[128][36];   // pad 36: 16B-aligned rows, low-conflict
    __shared__ float ps[32][64];

    const int tid = threadIdx.x;
    const int tx = tid & 15, ty = tid >> 4;
    const int rowbase = blockIdx.x * 128;

    unsigned long long acc[8][2];
#pragma unroll
    for (int i = 0; i < 8; i++) { acc[i][0] = 0ull; acc[i][1] = 0ull; }

    for (int kc = 0; kc < DIM; kc += 32) {
        // load x tile [128][32]
#pragma unroll
        for (int l = 0; l < 4; l++) {
            int lin = tid + l * 256;
            int row = lin >> 3, m = (lin & 7) << 2;
            float4 v = *(const float4*)&x[(size_t)(rowbase + row) * DIM + kc + m];
            *(float4*)&xs[row][m] = v;
        }
        // load proj tile [32][64]
#pragma unroll
        for (int l = 0; l < 2; l++) {
            int lin = tid + l * 256;
            int k = lin >> 4, n = (lin & 15) << 2;
            *(float4*)&ps[k][n] = *(const float4*)&proj[(size_t)(kc + k) * RANK + n];
        }
        __syncthreads();

#pragma unroll 8
        for (int k = 0; k < 32; k++) {
            unsigned long long b0 = *(const unsigned long long*)&ps[k][tx * 4];
            unsigned long long b1 = *(const unsigned long long*)&ps[k][tx * 4 + 2];
#pragma unroll
            for (int i = 0; i < 8; i++) {
                unsigned long long aa = pack2(xs[ty * 8 + i][k]);
                ffma2(acc[i][0], aa, b0);
                ffma2(acc[i][1], aa, b1);
            }
        }
        __syncthreads();
    }

#pragma unroll
    for (int i = 0; i < 8; i++) {
        float2 c0 = unpack2(acc[i][0]);
        float2 c1 = unpack2(acc[i][1]);
        float4 v = make_float4(c0.x, c0.y, c1.x, c1.y);
        *(float4*)&g_p[(size_t)(rowbase + ty * 8 + i) * RANK + tx * 4] = v;
    }
}

// ============================================================
// Kernel B: sq[i] = ||p_i||^2
// ============================================================
__global__ void __launch_bounds__(256) sq_kernel() {
    int row = blockIdx.x * 256 + threadIdx.x;
    const float4* pr = (const float4*)&g_p[(size_t)row * RANK];
    float s = 0.f;
#pragma unroll
    for (int i = 0; i < 16; i++) {
        float4 v = pr[i];
        s += v.x * v.x + v.y * v.y + v.z * v.z + v.w * v.w;
    }
    g_sq[row] = s;
}

// ============================================================
// Kernel C: dist[b,s,t] = max(sq_s + sq_t - 2 * <p_s, p_t>, 0)
// 128x128 output tile per CTA, 256 threads, 8x8 micro-tile, K=64 resident.
// ss: [128][64] row-major (a-reads warp-broadcast); tt: [64][132] k-major.
// ============================================================
#define TT_STRIDE 132
#define SMEM_C ((128 * 64 + 64 * TT_STRIDE) * 4)   // 66560 bytes

__global__ void __launch_bounds__(256, 2) dist_kernel(float* __restrict__ out) {
    extern __shared__ float smem[];
    float* ss = smem;               // 128*64
    float* tt = smem + 128 * 64;    // 64*132

    const int tid = threadIdx.x;
    const int tx = tid & 15, ty = tid >> 4;
    const int b = blockIdx.z;
    const int rowbase = b * SEQ + blockIdx.y * 128;
    const int colbase = b * SEQ + blockIdx.x * 128;

    // load ss (direct copy)
#pragma unroll
    for (int l = 0; l < 8; l++) {
        int lin = tid + l * 256;
        int row = lin >> 4, m = (lin & 15) << 2;
        *(float4*)&ss[row * 64 + m] =
            *(const float4*)&g_p[(size_t)(rowbase + row) * RANK + m];
    }
    // load tt (transposed to k-major)
#pragma unroll
    for (int l = 0; l < 8; l++) {
        int lin = tid + l * 256;
        int col = lin >> 4, m = (lin & 15) << 2;
        float4 v = *(const float4*)&g_p[(size_t)(colbase + col) * RANK + m];
        tt[(m + 0) * TT_STRIDE + col] = v.x;
        tt[(m + 1) * TT_STRIDE + col] = v.y;
        tt[(m + 2) * TT_STRIDE + col] = v.z;
        tt[(m + 3) * TT_STRIDE + col] = v.w;
    }
    __syncthreads();

    unsigned long long acc[8][4];
#pragma unroll
    for (int i = 0; i < 8; i++)
#pragma unroll
        for (int j = 0; j < 4; j++) acc[i][j] = 0ull;

#pragma unroll 4
    for (int k = 0; k < RANK; k++) {
        const float* ttk = &tt[k * TT_STRIDE + tx * 8];
        ulonglong2 b01 = *(const ulonglong2*)(ttk);
        ulonglong2 b23 = *(const ulonglong2*)(ttk + 4);
        unsigned long long aa[8];
#pragma unroll
        for (int i = 0; i < 8; i++) aa[i] = pack2(ss[(ty * 8 + i) * 64 + k]);
#pragma unroll
        for (int i = 0; i < 8; i++) {
            ffma2(acc[i][0], aa[i], b01.x);
            ffma2(acc[i][1], aa[i], b01.y);
            ffma2(acc[i][2], aa[i], b23.x);
            ffma2(acc[i][3], aa[i], b23.y);
        }
    }

    float sqs[8], sqt[8];
#pragma unroll
    for (int i = 0; i < 8; i++) sqs[i] = g_sq[rowbase + ty * 8 + i];
#pragma unroll
    for (int j = 0; j < 8; j++) sqt[j] = g_sq[colbase + tx * 8 + j];

    const size_t outbase = (size_t)b * SEQ * SEQ;
    const int orow0 = blockIdx.y * 128 + ty * 8;
    const int ocol = blockIdx.x * 128 + tx * 8;

#pragma unroll
    for (int i = 0; i < 8; i++) {
        float r[8];
#pragma unroll
        for (int j = 0; j < 4; j++) {
            float2 c = unpack2(acc[i][j]);
            r[2 * j + 0] = c.x;
            r[2 * j + 1] = c.y;
        }
        float4 v0, v1;
        v0.x = fmaxf(sqs[i] + sqt[0] - 2.f * r[0], 0.f);
        v0.y = fmaxf(sqs[i] + sqt[1] - 2.f * r[1], 0.f);
        v0.z = fmaxf(sqs[i] + sqt[2] - 2.f * r[2], 0.f);
        v0.w = fmaxf(sqs[i] + sqt[3] - 2.f * r[3], 0.f);
        v1.x = fmaxf(sqs[i] + sqt[4] - 2.f * r[4], 0.f);
        v1.y = fmaxf(sqs[i] + sqt[5] - 2.f * r[5], 0.f);
        v1.z = fmaxf(sqs[i] + sqt[6] - 2.f * r[6], 0.f);
        v1.w = fmaxf(sqs[i] + sqt[7] - 2.f * r[7], 0.f);
        float* op = &out[outbase + (size_t)(orow0 + i) * SEQ + ocol];
        *(float4*)(op) = v0;
        *(float4*)(op + 4) = v1;
    }
}

// ============================================================
extern "C" void kernel_launch(void* const* d_in, const int* in_sizes, int n_in,
                              void* d_out, int out_size) {
    const float* x = (const float*)d_in[0];
    const float* proj = (const float*)d_in[1];
    float* out = (float*)d_out;

    proj_kernel<<<NROW / 128, 256>>>(x, proj);
    sq_kernel<<<NROW / 256, 256>>>();

    cudaFuncSetAttribute(dist_kernel, cudaFuncAttributeMaxDynamicSharedMemorySize,
                         SMEM_C);
    dim3 grid(SEQ / 128, SEQ / 128, BB);
    dist_kernel<<<grid, 256, SMEM_C>>>(out);
}

// round 3
// speedup vs baseline: 2.2572x; 2.2572x over previous
#include <cuda_runtime.h>
#include <cstdint>

#define SEQ   4096
#define BATCH 4
#define DIM   1024
#define RANK  64
#define NROW  (BATCH * SEQ)     // 16384

// Scratch (__device__ globals per allocation rules).
// p stored twice, in mma A-fragment and B-fragment permuted layouts
// (per 128-row block: 8192 floats = 32KB).
__device__ float g_pA[NROW * RANK];
__device__ float g_pB[NROW * RANK];
__device__ float g_sq[NROW];

// ---------------- helpers ----------------
__device__ __forceinline__ uint32_t smem_u32(const void* p) {
    uint32_t a;
    asm("{ .reg .u64 t; cvta.to.shared.u64 t, %1; cvt.u32.u64 %0, t; }"
        : "=r"(a) : "l"(p));
    return a;
}
__device__ __forceinline__ void cpasync16(uint32_t s, const void* g) {
    asm volatile("cp.async.cg.shared.global [%0], [%1], 16;"
                 :: "r"(s), "l"(g) : "memory");
}
__device__ __forceinline__ uint32_t tf32u(float f) {
    uint32_t t;
    asm("cvt.rna.tf32.f32 %0, %1;" : "=r"(t) : "f"(f));
    return t;
}
__device__ __forceinline__ float tf32r(float f) {
    return __uint_as_float(tf32u(f));
}
// D += A(16x8,row) * B(8x8,col)   tf32 inputs, fp32 accum
__device__ __forceinline__ void mma_tf32(float* d, const uint32_t* a,
                                         uint32_t b0, uint32_t b1) {
    asm volatile(
        "mma.sync.aligned.m16n8k8.row.col.f32.tf32.tf32.f32 "
        "{%0,%1,%2,%3}, {%4,%5,%6,%7}, {%8,%9}, {%0,%1,%2,%3};"
        : "+f"(d[0]), "+f"(d[1]), "+f"(d[2]), "+f"(d[3])
        : "r"(a[0]), "r"(a[1]), "r"(a[2]), "r"(a[3]), "r"(b0), "r"(b1));
}

// ============================================================
// Kernel 1: proj. Per CTA: 128 rows x 64 cols, K=1024 in 16 chunks.
// x staged via cp.async double-buffer; proj staged pre-rounded in
// B-fragment order. Epilogue: round to tf32, sq norms, scatter to
// g_pA/g_pB fragment layouts.
// ============================================================
#define XS_STRIDE 68
#define XS_BUF (128 * XS_STRIDE)          // floats per x buffer
#define PS_BUF 4096                        // floats per proj buffer
#define PROJ_SMEM ((2 * XS_BUF + 2 * PS_BUF) * 4)

__global__ void __launch_bounds__(256) proj_mma_kernel(
    const float* __restrict__ x, const float* __restrict__ proj) {
    extern __shared__ float smf[];
    const int tid = threadIdx.x, wid = tid >> 5, lane = tid & 31;
    const int gid = lane >> 2, tig = lane & 3;
    const int rowbase = blockIdx.x * 128;
    const uint32_t sbase = smem_u32(smf);

    float acc[8][4];
#pragma unroll
    for (int i = 0; i < 8; i++)
#pragma unroll
        for (int j = 0; j < 4; j++) acc[i][j] = 0.f;

    auto load_x = [&](int it, int buf) {
        const float* src = x + (size_t)rowbase * DIM + it * 64;
#pragma unroll
        for (int l = 0; l < 8; l++) {
            int idx = tid + l * 256;
            int r = idx >> 4, c4 = (idx & 15) << 2;
            cpasync16(sbase + (uint32_t)(buf * XS_BUF + r * XS_STRIDE + c4) * 4,
                      src + (size_t)r * DIM + c4);
        }
    };
    auto load_p = [&](int it, int buf) {
        float* pd = smf + 2 * XS_BUF + buf * PS_BUF;
        const float* src = proj + (size_t)(it * 64) * RANK;
#pragma unroll
        for (int l = 0; l < 4; l++) {
            int idx = tid + l * 256;
            int kk = idx >> 4, n4 = (idx & 15) << 2;
            float4 v = *(const float4*)(src + (size_t)kk * RANK + n4);
            int kt = kk >> 3, f = (kk >> 2) & 1, k3 = kk & 3;
            const float* vp = (const float*)&v;
#pragma unroll
            for (int j = 0; j < 4; j++) {
                int n = n4 + j;
                pd[((n >> 3) * 8 + kt) * 64 + ((n & 7) * 4 + k3) * 2 + f] =
                    tf32r(vp[j]);
            }
        }
    };

    load_x(0, 0);
    asm volatile("cp.async.commit_group;" ::: "memory");
    load_p(0, 0);

    for (int it = 0; it < 16; ++it) {
        const int buf = it & 1;
        if (it < 15) {
            load_x(it + 1, buf ^ 1);
            asm volatile("cp.async.commit_group;" ::: "memory");
            load_p(it + 1, buf ^ 1);
            asm volatile("cp.async.wait_group 1;" ::: "memory");
        } else {
            asm volatile("cp.async.wait_group 0;" ::: "memory");
        }
        __syncthreads();

        const float* xb = smf + buf * XS_BUF;
        const float* pb = smf + 2 * XS_BUF + buf * PS_BUF;
        const int r0 = wid * 16 + gid;
#pragma unroll
        for (int kt = 0; kt < 8; kt++) {
            const int c = kt * 8 + tig;
            uint32_t a[4];
            a[0] = tf32u(xb[r0 * XS_STRIDE + c]);
            a[1] = tf32u(xb[(r0 + 8) * XS_STRIDE + c]);
            a[2] = tf32u(xb[r0 * XS_STRIDE + c + 4]);
            a[3] = tf32u(xb[(r0 + 8) * XS_STRIDE + c + 4]);
#pragma unroll
            for (int nt = 0; nt < 8; nt++) {
                const uint2 bb =
                    *(const uint2*)(pb + (nt * 8 + kt) * 64 + lane * 2);
                mma_tf32(acc[nt], a, bb.x, bb.y);
            }
        }
        __syncthreads();
    }

    // ---- epilogue: round, sq, scatter to fragment layouts ----
    float vals[8][4];
    float sq1 = 0.f, sq2 = 0.f;
#pragma unroll
    for (int nt = 0; nt < 8; nt++) {
#pragma unroll
        for (int j = 0; j < 4; j++) vals[nt][j] = tf32r(acc[nt][j]);
        sq1 += vals[nt][0] * vals[nt][0] + vals[nt][1] * vals[nt][1];
        sq2 += vals[nt][2] * vals[nt][2] + vals[nt][3] * vals[nt][3];
    }
    sq1 += __shfl_xor_sync(0xffffffffu, sq1, 1);
    sq1 += __shfl_xor_sync(0xffffffffu, sq1, 2);
    sq2 += __shfl_xor_sync(0xffffffffu, sq2, 1);
    sq2 += __shfl_xor_sync(0xffffffffu, sq2, 2);

    const int lr1 = wid * 16 + gid, lr2 = lr1 + 8;
    if (tig == 0) {
        g_sq[rowbase + lr1] = sq1;
        g_sq[rowbase + lr2] = sq2;
    }

    float* gA = g_pA + (size_t)blockIdx.x * 8192;
    float* gB = g_pB + (size_t)blockIdx.x * 8192;
#pragma unroll
    for (int nt = 0; nt < 8; nt++) {
#pragma unroll
        for (int jj = 0; jj < 4; jj++) {
            const int lr = (jj >= 2) ? lr2 : lr1;
            const int c = nt * 8 + 2 * tig + (jj & 1);
            const float v = vals[nt][jj];
            // A-fragment layout
            {
                int mt = lr >> 4, kt = c >> 3, rr = lr & 15, cc = c & 7;
                gA[(mt * 8 + kt) * 128 + ((rr & 7) * 4 + (cc & 3)) * 4 +
                   (rr >> 3) + 2 * (cc >> 2)] = v;
            }
            // B-fragment layout
            {
                int ntb = lr >> 3, kt = c >> 3, nn = lr & 7, kkb = c & 7;
                gB[(ntb * 8 + kt) * 64 + (nn * 4 + (kkb & 3)) * 2 +
                   (kkb >> 2)] = v;
            }
        }
    }
}

// ============================================================
// Kernel 2: dist. Per CTA: 128x128 tile; 8 warps, each 64x32.
// Identity cp.async copies of pre-permuted tiles; conflict-free
// lds.128/lds.64 fragment loads; fused epilogue.
// ============================================================
#define DIST_SMEM (16384 * 4)

__global__ void __launch_bounds__(256, 2) dist_mma_kernel(
    float* __restrict__ out) {
    extern __shared__ float smf[];
    __shared__ float s_sqA[128], s_sqB[128];

    const int tid = threadIdx.x, wid = tid >> 5, lane = tid & 31;
    const int gid = lane >> 2, tig = lane & 3;
    const int bx = blockIdx.x, by = blockIdx.y, bz = blockIdx.z;
    const int ablk = bz * 32 + by, bblk = bz * 32 + bx;
    const uint32_t sbase = smem_u32(smf);

    const float4* gA = (const float4*)(g_pA + (size_t)ablk * 8192);
    const float4* gB = (const float4*)(g_pB + (size_t)bblk * 8192);
#pragma unroll
    for (int l = 0; l < 8; l++) {
        int idx = tid + l * 256;
        cpasync16(sbase + (uint32_t)idx * 16, gA + idx);
        cpasync16(sbase + 32768u + (uint32_t)idx * 16, gB + idx);
    }
    asm volatile("cp.async.commit_group;" ::: "memory");
    if (tid < 128) s_sqA[tid] = g_sq[ablk * 128 + tid];
    else           s_sqB[tid - 128] = g_sq[bblk * 128 + (tid - 128)];
    asm volatile("cp.async.wait_group 0;" ::: "memory");
    __syncthreads();

    const int wm = wid & 1, wn = wid >> 1;
    const float* As = smf;
    const float* Bs = smf + 8192;

    float acc[4][4][4];
#pragma unroll
    for (int i = 0; i < 4; i++)
#pragma unroll
        for (int j = 0; j < 4; j++)
#pragma unroll
            for (int k = 0; k < 4; k++) acc[i][j][k] = 0.f;

#pragma unroll
    for (int kt = 0; kt < 8; kt++) {
        uint4 a[4];
        uint2 b[4];
#pragma unroll
        for (int mt = 0; mt < 4; mt++)
            a[mt] = *(const uint4*)(As + ((wm * 4 + mt) * 8 + kt) * 128 +
                                    lane * 4);
#pragma unroll
        for (int nt = 0; nt < 4; nt++)
            b[nt] = *(const uint2*)(Bs + ((wn * 4 + nt) * 8 + kt) * 64 +
                                    lane * 2);
#pragma unroll
        for (int mt = 0; mt < 4; mt++)
#pragma unroll
            for (int nt = 0; nt < 4; nt++)
                mma_tf32(acc[mt][nt], (const uint32_t*)&a[mt], b[nt].x,
                         b[nt].y);
    }

    // ---- fused epilogue ----
#pragma unroll
    for (int mt = 0; mt < 4; mt++) {
        const int rl1 = wm * 64 + mt * 16 + gid, rl2 = rl1 + 8;
        const float sA1 = s_sqA[rl1], sA2 = s_sqA[rl2];
        float* o1 = out + ((size_t)bz * SEQ + by * 128 + rl1) * SEQ + bx * 128;
        float* o2 = o1 + (size_t)8 * SEQ;
#pragma unroll
        for (int nt = 0; nt < 4; nt++) {
            const int cl = wn * 32 + nt * 8 + 2 * tig;
            const float sB0 = s_sqB[cl], sB1 = s_sqB[cl + 1];
            float2 v1, v2;
            v1.x = fmaxf(sA1 + sB0 - 2.f * acc[mt][nt][0], 0.f);
            v1.y = fmaxf(sA1 + sB1 - 2.f * acc[mt][nt][1], 0.f);
            v2.x = fmaxf(sA2 + sB0 - 2.f * acc[mt][nt][2], 0.f);
            v2.y = fmaxf(sA2 + sB1 - 2.f * acc[mt][nt][3], 0.f);
            *(float2*)(o1 + cl) = v1;
            *(float2*)(o2 + cl) = v2;
        }
    }
}

// ============================================================
extern "C" void kernel_launch(void* const* d_in, const int* in_sizes, int n_in,
                              void* d_out, int out_size) {
    const float* x = (const float*)d_in[0];
    const float* proj = (const float*)d_in[1];
    float* out = (float*)d_out;

    cudaFuncSetAttribute(proj_mma_kernel,
                         cudaFuncAttributeMaxDynamicSharedMemorySize, PROJ_SMEM);
    proj_mma_kernel<<<NROW / 128, 256, PROJ_SMEM>>>(x, proj);

    cudaFuncSetAttribute(dist_mma_kernel,
                         cudaFuncAttributeMaxDynamicSharedMemorySize, DIST_SMEM);
    dim3 grid(SEQ / 128, SEQ / 128, BATCH);
    dist_mma_kernel<<<grid, 256, DIST_SMEM>>>(out);
}

// round 4
// speedup vs baseline: 3.2000x; 1.4177x over previous
#include <cuda_runtime.h>
#include <cstdint>

#define SEQ   4096
#define BATCH 4
#define DIM   1024
#define RANK  64
#define NROW  (BATCH * SEQ)   // 16384
#define NTILE 32              // 128-row blocks per batch
#define TRI   528             // upper-tri tiles per batch (32*33/2)

// Scratch (__device__ globals per allocation rules)
__device__ float g_pA[NROW * RANK];   // p, A-fragment layout (32KB / 128-row blk)
__device__ float g_pB[NROW * RANK];   // p, B-fragment layout
__device__ float g_sq[NROW];          // row squared norms (of tf32-rounded p)
__device__ float g_pf[DIM * RANK];    // proj tf32 B-fragments, 16 chunks of 4096

// ---------------- helpers ----------------
__device__ __forceinline__ uint32_t smem_u32(const void* p) {
    uint32_t a;
    asm("{ .reg .u64 t; cvta.to.shared.u64 t, %1; cvt.u32.u64 %0, t; }"
        : "=r"(a) : "l"(p));
    return a;
}
__device__ __forceinline__ void cpasync16(uint32_t s, const void* g) {
    asm volatile("cp.async.cg.shared.global [%0], [%1], 16;"
                 :: "r"(s), "l"(g) : "memory");
}
__device__ __forceinline__ uint32_t tf32u(float f) {
    uint32_t t;
    asm("cvt.rna.tf32.f32 %0, %1;" : "=r"(t) : "f"(f));
    return t;
}
__device__ __forceinline__ float tf32r(float f) { return __uint_as_float(tf32u(f)); }
__device__ __forceinline__ void mma_tf32(float* d, const uint32_t* a,
                                         uint32_t b0, uint32_t b1) {
    asm volatile(
        "mma.sync.aligned.m16n8k8.row.col.f32.tf32.tf32.f32 "
        "{%0,%1,%2,%3}, {%4,%5,%6,%7}, {%8,%9}, {%0,%1,%2,%3};"
        : "+f"(d[0]), "+f"(d[1]), "+f"(d[2]), "+f"(d[3])
        : "r"(a[0]), "r"(a[1]), "r"(a[2]), "r"(a[3]), "r"(b0), "r"(b1));
}

// ============================================================
// Kernel 0: proj -> tf32 B-fragment chunks (once).
// ============================================================
__global__ void __launch_bounds__(256) prep_proj_kernel(
    const float* __restrict__ proj) {
    int idx = blockIdx.x * 256 + threadIdx.x;   // 65536 = 1024*64
    int k = idx >> 6, n = idx & 63;
    int chunk = k >> 6, kk = k & 63;
    int kt = kk >> 3, f = (kk >> 2) & 1, k3 = kk & 3;
    g_pf[chunk * 4096 + ((n >> 3) * 8 + kt) * 64 + ((n & 7) * 4 + k3) * 2 + f] =
        tf32r(proj[idx]);
}

// ============================================================
// Kernel 1: proj GEMM. 256 CTAs x 64 rows, K=1024 in 16 chunks.
// Warps: 4 in M (16 rows) x 2 in N (32 cols). cp.async double buffer,
// identity copies of pre-built proj fragments.
// ============================================================
#define XST 68
#define XBUF (64 * XST)
#define PBUF 4096
#define PROJ_SMEM ((2 * XBUF + 2 * PBUF) * 4)

__global__ void __launch_bounds__(256, 2) proj_mma_kernel(
    const float* __restrict__ x) {
    extern __shared__ float smf[];
    __shared__ float s_part[2][64];

    const int tid = threadIdx.x, wid = tid >> 5, lane = tid & 31;
    const int gid = lane >> 2, tig = lane & 3;
    const int wm = wid & 3, wn = wid >> 2;
    const int rowbase = blockIdx.x * 64;
    const uint32_t sbase = smem_u32(smf);

    float acc[4][4];
#pragma unroll
    for (int i = 0; i < 4; i++)
#pragma unroll
        for (int j = 0; j < 4; j++) acc[i][j] = 0.f;

    auto load_stage = [&](int it, int buf) {
        const float* src = x + (size_t)rowbase * DIM + it * 64;
#pragma unroll
        for (int l = 0; l < 4; l++) {
            int idx = tid + l * 256;
            int r = idx >> 4, c4 = (idx & 15) << 2;
            cpasync16(sbase + (uint32_t)(buf * XBUF + r * XST + c4) * 4,
                      src + (size_t)r * DIM + c4);
        }
        const float* pf = g_pf + it * PBUF;
#pragma unroll
        for (int l = 0; l < 4; l++) {
            int idx = tid + l * 256;
            cpasync16(sbase + (uint32_t)(2 * XBUF + buf * PBUF + idx * 4) * 4,
                      pf + idx * 4);
        }
        asm volatile("cp.async.commit_group;" ::: "memory");
    };

    load_stage(0, 0);

    for (int it = 0; it < 16; ++it) {
        const int buf = it & 1;
        if (it < 15) {
            load_stage(it + 1, buf ^ 1);
            asm volatile("cp.async.wait_group 1;" ::: "memory");
        } else {
            asm volatile("cp.async.wait_group 0;" ::: "memory");
        }
        __syncthreads();

        const float* xb = smf + buf * XBUF;
        const float* pb = smf + 2 * XBUF + buf * PBUF;
        const int r0 = wm * 16 + gid;
#pragma unroll
        for (int kt = 0; kt < 8; kt++) {
            const int c = kt * 8 + tig;
            uint32_t a[4];
            a[0] = tf32u(xb[r0 * XST + c]);
            a[1] = tf32u(xb[(r0 + 8) * XST + c]);
            a[2] = tf32u(xb[r0 * XST + c + 4]);
            a[3] = tf32u(xb[(r0 + 8) * XST + c + 4]);
#pragma unroll
            for (int nt = 0; nt < 4; nt++) {
                const int ng = wn * 4 + nt;
                const uint2 bb = *(const uint2*)(pb + (ng * 8 + kt) * 64 + lane * 2);
                mma_tf32(acc[nt], a, bb.x, bb.y);
            }
        }
        __syncthreads();
    }

    // ---- epilogue: round to tf32, sq norms, scatter to fragment layouts ----
    float vals[4][4];
    float sq1 = 0.f, sq2 = 0.f;
#pragma unroll
    for (int nt = 0; nt < 4; nt++) {
#pragma unroll
        for (int j = 0; j < 4; j++) vals[nt][j] = tf32r(acc[nt][j]);
        sq1 += vals[nt][0] * vals[nt][0] + vals[nt][1] * vals[nt][1];
        sq2 += vals[nt][2] * vals[nt][2] + vals[nt][3] * vals[nt][3];
    }
    sq1 += __shfl_xor_sync(0xffffffffu, sq1, 1);
    sq1 += __shfl_xor_sync(0xffffffffu, sq1, 2);
    sq2 += __shfl_xor_sync(0xffffffffu, sq2, 1);
    sq2 += __shfl_xor_sync(0xffffffffu, sq2, 2);

    const int r1 = wm * 16 + gid, r2 = r1 + 8;
    if (tig == 0) {
        s_part[wn][r1] = sq1;
        s_part[wn][r2] = sq2;
    }
    __syncthreads();
    if (tid < 64) g_sq[rowbase + tid] = s_part[0][tid] + s_part[1][tid];

    const int bb = blockIdx.x >> 1;
    const int half = (blockIdx.x & 1) * 64;
    float* gA = g_pA + (size_t)bb * 8192;
    float* gB = g_pB + (size_t)bb * 8192;
#pragma unroll
    for (int nt = 0; nt < 4; nt++) {
#pragma unroll
        for (int jj = 0; jj < 4; jj++) {
            const int lr = half + ((jj >= 2) ? r2 : r1);
            const int c = wn * 32 + nt * 8 + 2 * tig + (jj & 1);
            const float v = vals[nt][jj];
            {   // A-fragment layout
                int mt = lr >> 4, kt = c >> 3, rr = lr & 15, cc = c & 7;
                gA[(mt * 8 + kt) * 128 + ((rr & 7) * 4 + (cc & 3)) * 4 +
                   (rr >> 3) + 2 * (cc >> 2)] = v;
            }
            {   // B-fragment layout
                int ntb = lr >> 3, kt = c >> 3, nn = lr & 7, kkb = c & 7;
                gB[(ntb * 8 + kt) * 64 + (nn * 4 + (kkb & 3)) * 2 + (kkb >> 2)] = v;
            }
        }
    }
}

// ============================================================
// Kernel 2: dist, symmetric. One CTA per upper-tri 128x128 tile.
// Direct write from regs; off-diagonal also writes the transposed
// tile via padded smem (stride 140: conflict-free STS + coalesced STG).
// ============================================================
#define TS_STRIDE 140
#define DIST_SMEM (128 * TS_STRIDE * 4)   // 71680 > 2*32768 tile area

__global__ void __launch_bounds__(256, 2) dist_mma_kernel(
    float* __restrict__ out) {
    extern __shared__ float smf[];
    __shared__ float s_sqA[128], s_sqB[128];

    const int tid = threadIdx.x, wid = tid >> 5, lane = tid & 31;
    const int gid = lane >> 2, tig = lane & 3;
    const int bz = blockIdx.z;

    // decode upper-triangular (i <= j) tile index
    const int t = blockIdx.x;
    int i = (int)(32.5f - sqrtf(32.5f * 32.5f - 2.0f * (float)t));
    if (i > 31) i = 31;
    while (i > 0 && (i * 32 - i * (i - 1) / 2) > t) i--;
    while (((i + 1) * 32 - (i + 1) * i / 2) <= t) i++;
    const int j = i + (t - (i * 32 - i * (i - 1) / 2));

    const int ablk = bz * NTILE + i, bblk = bz * NTILE + j;
    const uint32_t sbase = smem_u32(smf);

    const float4* gA = (const float4*)(g_pA + (size_t)ablk * 8192);
    const float4* gB = (const float4*)(g_pB + (size_t)bblk * 8192);
#pragma unroll
    for (int l = 0; l < 8; l++) {
        int idx = tid + l * 256;
        cpasync16(sbase + (uint32_t)idx * 16, gA + idx);
        cpasync16(sbase + 32768u + (uint32_t)idx * 16, gB + idx);
    }
    asm volatile("cp.async.commit_group;" ::: "memory");
    if (tid < 128) s_sqA[tid] = g_sq[ablk * 128 + tid];
    else           s_sqB[tid - 128] = g_sq[bblk * 128 + (tid - 128)];
    asm volatile("cp.async.wait_group 0;" ::: "memory");
    __syncthreads();

    const int wm = wid & 1, wn = wid >> 1;
    const float* As = smf;
    const float* Bs = smf + 8192;

    float acc[4][4][4];
#pragma unroll
    for (int a = 0; a < 4; a++)
#pragma unroll
        for (int b = 0; b < 4; b++)
#pragma unroll
            for (int c = 0; c < 4; c++) acc[a][b][c] = 0.f;

#pragma unroll
    for (int kt = 0; kt < 8; kt++) {
        uint4 a[4];
        uint2 b[4];
#pragma unroll
        for (int mt = 0; mt < 4; mt++)
            a[mt] = *(const uint4*)(As + ((wm * 4 + mt) * 8 + kt) * 128 + lane * 4);
#pragma unroll
        for (int nt = 0; nt < 4; nt++)
            b[nt] = *(const uint2*)(Bs + ((wn * 4 + nt) * 8 + kt) * 64 + lane * 2);
#pragma unroll
        for (int mt = 0; mt < 4; mt++)
#pragma unroll
            for (int nt = 0; nt < 4; nt++)
                mma_tf32(acc[mt][nt], (const uint32_t*)&a[mt], b[nt].x, b[nt].y);
    }

    // ---- finalize values (clamped distances) in regs ----
#pragma unroll
    for (int mt = 0; mt < 4; mt++) {
        const int rl1 = wm * 64 + mt * 16 + gid, rl2 = rl1 + 8;
        const float sA1 = s_sqA[rl1], sA2 = s_sqA[rl2];
#pragma unroll
        for (int nt = 0; nt < 4; nt++) {
            const int cl = wn * 32 + nt * 8 + 2 * tig;
            const float sB0 = s_sqB[cl], sB1 = s_sqB[cl + 1];
            acc[mt][nt][0] = fmaxf(sA1 + sB0 - 2.f * acc[mt][nt][0], 0.f);
            acc[mt][nt][1] = fmaxf(sA1 + sB1 - 2.f * acc[mt][nt][1], 0.f);
            acc[mt][nt][2] = fmaxf(sA2 + sB0 - 2.f * acc[mt][nt][2], 0.f);
            acc[mt][nt][3] = fmaxf(sA2 + sB1 - 2.f * acc[mt][nt][3], 0.f);
        }
    }

    // ---- direct tile write (rows i-block, cols j-block) ----
#pragma unroll
    for (int mt = 0; mt < 4; mt++) {
        const int rl1 = wm * 64 + mt * 16 + gid;
        float* o1 = out + ((size_t)bz * SEQ + i * 128 + rl1) * SEQ + j * 128;
        float* o2 = o1 + (size_t)8 * SEQ;
#pragma unroll
        for (int nt = 0; nt < 4; nt++) {
            const int cl = wn * 32 + nt * 8 + 2 * tig;
            *(float2*)(o1 + cl) = make_float2(acc[mt][nt][0], acc[mt][nt][1]);
            *(float2*)(o2 + cl) = make_float2(acc[mt][nt][2], acc[mt][nt][3]);
        }
    }

    // ---- transposed tile write (off-diagonal only) ----
    if (i != j) {
        __syncthreads();   // done reading As/Bs; reuse smem as transpose buffer
        float* Ts = smf;
#pragma unroll
        for (int mt = 0; mt < 4; mt++) {
            const int rl1 = wm * 64 + mt * 16 + gid, rl2 = rl1 + 8;
#pragma unroll
            for (int nt = 0; nt < 4; nt++) {
                const int cl = wn * 32 + nt * 8 + 2 * tig;
                Ts[(cl + 0) * TS_STRIDE + rl1] = acc[mt][nt][0];
                Ts[(cl + 1) * TS_STRIDE + rl1] = acc[mt][nt][1];
                Ts[(cl + 0) * TS_STRIDE + rl2] = acc[mt][nt][2];
                Ts[(cl + 1) * TS_STRIDE + rl2] = acc[mt][nt][3];
            }
        }
        __syncthreads();
#pragma unroll
        for (int l = 0; l < 16; l++) {
            int idx = tid + l * 256;
            int c = idx >> 5, r4 = (idx & 31) << 2;
            float4 v = *(const float4*)(Ts + c * TS_STRIDE + r4);
            *(float4*)(out + ((size_t)bz * SEQ + j * 128 + c) * SEQ + i * 128 + r4) = v;
        }
    }
}

// ============================================================
extern "C" void kernel_launch(void* const* d_in, const int* in_sizes, int n_in,
                              void* d_out, int out_size) {
    const float* x = (const float*)d_in[0];
    const float* proj = (const float*)d_in[1];
    float* out = (float*)d_out;

    prep_proj_kernel<<<256, 256>>>(proj);

    cudaFuncSetAttribute(proj_mma_kernel,
                         cudaFuncAttributeMaxDynamicSharedMemorySize, PROJ_SMEM);
    proj_mma_kernel<<<NROW / 64, 256, PROJ_SMEM>>>(x);

    cudaFuncSetAttribute(dist_mma_kernel,
                         cudaFuncAttributeMaxDynamicSharedMemorySize, DIST_SMEM);
    dim3 grid(TRI, 1, BATCH);
    dist_mma_kernel<<<grid, 256, DIST_SMEM>>>(out);
}

// round 5
// speedup vs baseline: 3.2599x; 1.0187x over previous
#include <cuda_runtime.h>
#include <cstdint>

#define SEQ   4096
#define BATCH 4
#define DIM   1024
#define RANK  64
#define NROW  (BATCH * SEQ)   // 16384
#define NTILE 32              // 128-row blocks per batch
#define TRI   528             // upper-tri tiles per batch (32*33/2)

// Scratch (__device__ globals per allocation rules)
__device__ float g_pA[NROW * RANK];   // p, A-fragment layout (32KB / 128-row blk)
__device__ float g_pB[NROW * RANK];   // p, B-fragment layout
__device__ float g_sq[NROW];          // row squared norms (of tf32-rounded p)
__device__ float g_pf[DIM * RANK];    // proj tf32 B-fragments, 16 chunks of 4096

// ---------------- helpers ----------------
__device__ __forceinline__ uint32_t smem_u32(const void* p) {
    uint32_t a;
    asm("{ .reg .u64 t; cvta.to.shared.u64 t, %1; cvt.u32.u64 %0, t; }"
        : "=r"(a) : "l"(p));
    return a;
}
__device__ __forceinline__ void cpasync16(uint32_t s, const void* g) {
    asm volatile("cp.async.cg.shared.global [%0], [%1], 16;"
                 :: "r"(s), "l"(g) : "memory");
}
__device__ __forceinline__ uint32_t tf32u(float f) {
    uint32_t t;
    asm("cvt.rna.tf32.f32 %0, %1;" : "=r"(t) : "f"(f));
    return t;
}
__device__ __forceinline__ float tf32r(float f) { return __uint_as_float(tf32u(f)); }
__device__ __forceinline__ void mma_tf32(float* d, const uint32_t* a,
                                         uint32_t b0, uint32_t b1) {
    asm volatile(
        "mma.sync.aligned.m16n8k8.row.col.f32.tf32.tf32.f32 "
        "{%0,%1,%2,%3}, {%4,%5,%6,%7}, {%8,%9}, {%0,%1,%2,%3};"
        : "+f"(d[0]), "+f"(d[1]), "+f"(d[2]), "+f"(d[3])
        : "r"(a[0]), "r"(a[1]), "r"(a[2]), "r"(a[3]), "r"(b0), "r"(b1));
}

// ============================================================
// Kernel 0: proj -> tf32 B-fragment chunks (once). float4-vectorized.
// ============================================================
__global__ void __launch_bounds__(256) prep_proj_kernel(
    const float* __restrict__ proj) {
    int idx = blockIdx.x * 256 + threadIdx.x;   // 16384 float4s = 1024*64 floats
    int k = idx >> 4, n4 = (idx & 15) << 2;
    float4 v = *(const float4*)(proj + (size_t)k * RANK + n4);
    int chunk = k >> 6, kk = k & 63;
    int kt = kk >> 3, f = (kk >> 2) & 1, k3 = kk & 3;
    float* dst = g_pf + chunk * 4096;
    const float* vp = (const float*)&v;
#pragma unroll
    for (int j = 0; j < 4; j++) {
        int n = n4 + j;
        dst[((n >> 3) * 8 + kt) * 64 + ((n & 7) * 4 + k3) * 2 + f] = tf32r(vp[j]);
    }
}

// ============================================================
// Kernel 1: proj GEMM. 256 CTAs x 64 rows, K=1024 in 16 chunks.
// 3-stage cp.async pipeline (hides ~2x DRAM latency).
// Warps: 4 in M (16 rows) x 2 in N (32 cols).
// ============================================================
#define XST 68
#define XBUF (64 * XST)          // 4352 floats
#define PBUF 4096                // floats
#define STAGE (XBUF + PBUF)      // 8448 floats = 33792 B
#define PROJ_SMEM (3 * STAGE * 4)  // 101376 B -> 2 CTA/SM

__global__ void __launch_bounds__(256, 2) proj_mma_kernel(
    const float* __restrict__ x) {
    extern __shared__ float smf[];
    __shared__ float s_part[2][64];

    const int tid = threadIdx.x, wid = tid >> 5, lane = tid & 31;
    const int gid = lane >> 2, tig = lane & 3;
    const int wm = wid & 3, wn = wid >> 2;
    const int rowbase = blockIdx.x * 64;
    const uint32_t sbase = smem_u32(smf);

    float acc[4][4];
#pragma unroll
    for (int i = 0; i < 4; i++)
#pragma unroll
        for (int j = 0; j < 4; j++) acc[i][j] = 0.f;

    auto load_stage = [&](int it, int buf) {
        const uint32_t sb = sbase + (uint32_t)(buf * STAGE) * 4;
        const float* src = x + (size_t)rowbase * DIM + it * 64;
#pragma unroll
        for (int l = 0; l < 4; l++) {
            int idx = tid + l * 256;
            int r = idx >> 4, c4 = (idx & 15) << 2;
            cpasync16(sb + (uint32_t)(r * XST + c4) * 4,
                      src + (size_t)r * DIM + c4);
        }
        const float* pf = g_pf + it * PBUF;
#pragma unroll
        for (int l = 0; l < 4; l++) {
            int idx = tid + l * 256;
            cpasync16(sb + (uint32_t)(XBUF + idx * 4) * 4, pf + idx * 4);
        }
        asm volatile("cp.async.commit_group;" ::: "memory");
    };

    load_stage(0, 0);
    load_stage(1, 1);
    load_stage(2, 2);

    int buf = 0;
    for (int it = 0; it < 16; ++it) {
        if (it <= 13)      asm volatile("cp.async.wait_group 2;" ::: "memory");
        else if (it == 14) asm volatile("cp.async.wait_group 1;" ::: "memory");
        else               asm volatile("cp.async.wait_group 0;" ::: "memory");
        __syncthreads();

        const float* xb = smf + buf * STAGE;
        const float* pb = xb + XBUF;
        const int r0 = wm * 16 + gid;
#pragma unroll
        for (int kt = 0; kt < 8; kt++) {
            const int c = kt * 8 + tig;
            uint32_t a[4];
            a[0] = tf32u(xb[r0 * XST + c]);
            a[1] = tf32u(xb[(r0 + 8) * XST + c]);
            a[2] = tf32u(xb[r0 * XST + c + 4]);
            a[3] = tf32u(xb[(r0 + 8) * XST + c + 4]);
#pragma unroll
            for (int nt = 0; nt < 4; nt++) {
                const int ng = wn * 4 + nt;
                const uint2 bb = *(const uint2*)(pb + (ng * 8 + kt) * 64 + lane * 2);
                mma_tf32(acc[nt], a, bb.x, bb.y);
            }
        }
        __syncthreads();   // all warps done with buf before refill
        if (it + 3 < 16) load_stage(it + 3, buf);
        buf = (buf == 2) ? 0 : buf + 1;
    }

    // ---- epilogue: round to tf32, sq norms, scatter to fragment layouts ----
    float vals[4][4];
    float sq1 = 0.f, sq2 = 0.f;
#pragma unroll
    for (int nt = 0; nt < 4; nt++) {
#pragma unroll
        for (int j = 0; j < 4; j++) vals[nt][j] = tf32r(acc[nt][j]);
        sq1 += vals[nt][0] * vals[nt][0] + vals[nt][1] * vals[nt][1];
        sq2 += vals[nt][2] * vals[nt][2] + vals[nt][3] * vals[nt][3];
    }
    sq1 += __shfl_xor_sync(0xffffffffu, sq1, 1);
    sq1 += __shfl_xor_sync(0xffffffffu, sq1, 2);
    sq2 += __shfl_xor_sync(0xffffffffu, sq2, 1);
    sq2 += __shfl_xor_sync(0xffffffffu, sq2, 2);

    const int r1 = wm * 16 + gid, r2 = r1 + 8;
    if (tig == 0) {
        s_part[wn][r1] = sq1;
        s_part[wn][r2] = sq2;
    }
    __syncthreads();
    if (tid < 64) g_sq[rowbase + tid] = s_part[0][tid] + s_part[1][tid];

    const int bb = blockIdx.x >> 1;
    const int half = (blockIdx.x & 1) * 64;
    float* gA = g_pA + (size_t)bb * 8192;
    float* gB = g_pB + (size_t)bb * 8192;
#pragma unroll
    for (int nt = 0; nt < 4; nt++) {
#pragma unroll
        for (int jj = 0; jj < 4; jj++) {
            const int lr = half + ((jj >= 2) ? r2 : r1);
            const int c = wn * 32 + nt * 8 + 2 * tig + (jj & 1);
            const float v = vals[nt][jj];
            {   // A-fragment layout
                int mt = lr >> 4, kt = c >> 3, rr = lr & 15, cc = c & 7;
                gA[(mt * 8 + kt) * 128 + ((rr & 7) * 4 + (cc & 3)) * 4 +
                   (rr >> 3) + 2 * (cc >> 2)] = v;
            }
            {   // B-fragment layout
                int ntb = lr >> 3, kt = c >> 3, nn = lr & 7, kkb = c & 7;
                gB[(ntb * 8 + kt) * 64 + (nn * 4 + (kkb & 3)) * 2 + (kkb >> 2)] = v;
            }
        }
    }
}

// ============================================================
// Kernel 2: dist, symmetric. One CTA per upper-tri 128x128 tile.
// Output stores use __stcs (evict-first: output is write-once).
// Off-diagonal tiles also write transposed copy via padded smem.
// ============================================================
#define TS_STRIDE 140
#define DIST_SMEM (128 * TS_STRIDE * 4)   // 71680 B

__global__ void __launch_bounds__(256, 2) dist_mma_kernel(
    float* __restrict__ out) {
    extern __shared__ float smf[];
    __shared__ float s_sqA[128], s_sqB[128];

    const int tid = threadIdx.x, wid = tid >> 5, lane = tid & 31;
    const int gid = lane >> 2, tig = lane & 3;
    const int bz = blockIdx.z;

    // decode upper-triangular (i <= j) tile index
    const int t = blockIdx.x;
    int i = (int)(32.5f - sqrtf(32.5f * 32.5f - 2.0f * (float)t));
    if (i > 31) i = 31;
    while (i > 0 && (i * 32 - i * (i - 1) / 2) > t) i--;
    while (((i + 1) * 32 - (i + 1) * i / 2) <= t) i++;
    const int j = i + (t - (i * 32 - i * (i - 1) / 2));

    const int ablk = bz * NTILE + i, bblk = bz * NTILE + j;
    const uint32_t sbase = smem_u32(smf);

    const float4* gA = (const float4*)(g_pA + (size_t)ablk * 8192);
    const float4* gB = (const float4*)(g_pB + (size_t)bblk * 8192);
#pragma unroll
    for (int l = 0; l < 8; l++) {
        int idx = tid + l * 256;
        cpasync16(sbase + (uint32_t)idx * 16, gA + idx);
        cpasync16(sbase + 32768u + (uint32_t)idx * 16, gB + idx);
    }
    asm volatile("cp.async.commit_group;" ::: "memory");
    if (tid < 128) s_sqA[tid] = g_sq[ablk * 128 + tid];
    else           s_sqB[tid - 128] = g_sq[bblk * 128 + (tid - 128)];
    asm volatile("cp.async.wait_group 0;" ::: "memory");
    __syncthreads();

    const int wm = wid & 1, wn = wid >> 1;
    const float* As = smf;
    const float* Bs = smf + 8192;

    float acc[4][4][4];
#pragma unroll
    for (int a = 0; a < 4; a++)
#pragma unroll
        for (int b = 0; b < 4; b++)
#pragma unroll
            for (int c = 0; c < 4; c++) acc[a][b][c] = 0.f;

#pragma unroll
    for (int kt = 0; kt < 8; kt++) {
        uint4 a[4];
        uint2 b[4];
#pragma unroll
        for (int mt = 0; mt < 4; mt++)
            a[mt] = *(const uint4*)(As + ((wm * 4 + mt) * 8 + kt) * 128 + lane * 4);
#pragma unroll
        for (int nt = 0; nt < 4; nt++)
            b[nt] = *(const uint2*)(Bs + ((wn * 4 + nt) * 8 + kt) * 64 + lane * 2);
#pragma unroll
        for (int mt = 0; mt < 4; mt++)
#pragma unroll
            for (int nt = 0; nt < 4; nt++)
                mma_tf32(acc[mt][nt], (const uint32_t*)&a[mt], b[nt].x, b[nt].y);
    }

    // ---- finalize values (clamped distances) in regs ----
#pragma unroll
    for (int mt = 0; mt < 4; mt++) {
        const int rl1 = wm * 64 + mt * 16 + gid, rl2 = rl1 + 8;
        const float sA1 = s_sqA[rl1], sA2 = s_sqA[rl2];
#pragma unroll
        for (int nt = 0; nt < 4; nt++) {
            const int cl = wn * 32 + nt * 8 + 2 * tig;
            const float sB0 = s_sqB[cl], sB1 = s_sqB[cl + 1];
            acc[mt][nt][0] = fmaxf(sA1 + sB0 - 2.f * acc[mt][nt][0], 0.f);
            acc[mt][nt][1] = fmaxf(sA1 + sB1 - 2.f * acc[mt][nt][1], 0.f);
            acc[mt][nt][2] = fmaxf(sA2 + sB0 - 2.f * acc[mt][nt][2], 0.f);
            acc[mt][nt][3] = fmaxf(sA2 + sB1 - 2.f * acc[mt][nt][3], 0.f);
        }
    }

    // ---- direct tile write (rows i-block, cols j-block), evict-first ----
#pragma unroll
    for (int mt = 0; mt < 4; mt++) {
        const int rl1 = wm * 64 + mt * 16 + gid;
        float* o1 = out + ((size_t)bz * SEQ + i * 128 + rl1) * SEQ + j * 128;
        float* o2 = o1 + (size_t)8 * SEQ;
#pragma unroll
        for (int nt = 0; nt < 4; nt++) {
            const int cl = wn * 32 + nt * 8 + 2 * tig;
            __stcs((float2*)(o1 + cl), make_float2(acc[mt][nt][0], acc[mt][nt][1]));
            __stcs((float2*)(o2 + cl), make_float2(acc[mt][nt][2], acc[mt][nt][3]));
        }
    }

    // ---- transposed tile write (off-diagonal only) ----
    if (i != j) {
        __syncthreads();   // done reading As/Bs; reuse smem as transpose buffer
        float* Ts = smf;
#pragma unroll
        for (int mt = 0; mt < 4; mt++) {
            const int rl1 = wm * 64 + mt * 16 + gid, rl2 = rl1 + 8;
#pragma unroll
            for (int nt = 0; nt < 4; nt++) {
                const int cl = wn * 32 + nt * 8 + 2 * tig;
                Ts[(cl + 0) * TS_STRIDE + rl1] = acc[mt][nt][0];
                Ts[(cl + 1) * TS_STRIDE + rl1] = acc[mt][nt][1];
                Ts[(cl + 0) * TS_STRIDE + rl2] = acc[mt][nt][2];
                Ts[(cl + 1) * TS_STRIDE + rl2] = acc[mt][nt][3];
            }
        }
        __syncthreads();
#pragma unroll
        for (int l = 0; l < 16; l++) {
            int idx = tid + l * 256;
            int c = idx >> 5, r4 = (idx & 31) << 2;
            float4 v = *(const float4*)(Ts + c * TS_STRIDE + r4);
            __stcs((float4*)(out + ((size_t)bz * SEQ + j * 128 + c) * SEQ +
                             i * 128 + r4), v);
        }
    }
}

// ============================================================
extern "C" void kernel_launch(void* const* d_in, const int* in_sizes, int n_in,
                              void* d_out, int out_size) {
    const float* x = (const float*)d_in[0];
    const float* proj = (const float*)d_in[1];
    float* out = (float*)d_out;

    prep_proj_kernel<<<64, 256>>>(proj);

    cudaFuncSetAttribute(proj_mma_kernel,
                         cudaFuncAttributeMaxDynamicSharedMemorySize, PROJ_SMEM);
    proj_mma_kernel<<<NROW / 64, 256, PROJ_SMEM>>>(x);

    cudaFuncSetAttribute(dist_mma_kernel,
                         cudaFuncAttributeMaxDynamicSharedMemorySize, DIST_SMEM);
    dim3 grid(TRI, 1, BATCH);
    dist_mma_kernel<<<grid, 256, DIST_SMEM>>>(out);
}